// round 4
// baseline (speedup 1.0000x reference)
#include <cuda_runtime.h>
#include <cstdint>

#define BB 32
#define HH 56
#define HC 128
#define CC 256
#define PIX (HH*HH)          // 3136
#define EZ (BB*HC*PIX)       // 12845056
#define N1 (BB*PIX)          // 100352
#define OHH 112
#define OPIX (OHH*OHH)       // 12544
#define N2 (BB*OPIX)         // 401408
#define KW1 (257*9)          // 2313

__device__ __align__(128) float g_z[EZ];        // conv1 out -> (in place) BEC output h
__device__ __align__(128) float g_wp[KW1*128];  // repacked w1: [ic*9+kk][oc]
__device__ __align__(128) float g_Ah[1024*128]; // dec A hi (tf32-rounded), [m][k]
__device__ __align__(128) float g_Al[1024*128]; // dec A lo (tf32-rounded residual)
__device__ float g_m1[HC], g_rs1[HC];
__device__ float g_m2[CC], g_rs2[CC];

// ---------------------------------------------------------------------------
// Kernel 0a: repack w1 [oc][ic][kk] -> g_wp [ic*9+kk][oc]
// ---------------------------------------------------------------------------
__global__ __launch_bounds__(256) void repack_kernel(const float* __restrict__ w1) {
  int i = blockIdx.x * 256 + threadIdx.x;
  if (i < KW1 * 128) {
    int oc = i & 127, ickk = i >> 7;
    g_wp[ickk * 128 + oc] = w1[oc * KW1 + ickk];
  }
}

// ---------------------------------------------------------------------------
// Kernel 0b: prepack dec A = w4^T  [m=(c*4+tap)][k=hc], split tf32 hi/lo
// ---------------------------------------------------------------------------
__global__ __launch_bounds__(256) void prepA_kernel(const float* __restrict__ w4) {
  int i = blockIdx.x * 256 + threadIdx.x;
  if (i < 1024 * 128) {
    int m = i >> 7, k = i & 127;
    float w = w4[k * 1024 + m];
    uint32_t hb;
    asm("cvt.rna.tf32.f32 %0, %1;" : "=r"(hb) : "f"(w));
    float hi = __uint_as_float(hb);
    float lo = w - hi;
    uint32_t lb;
    asm("cvt.rna.tf32.f32 %0, %1;" : "=r"(lb) : "f"(lo));
    g_Ah[m * 128 + k] = hi;
    g_Al[m * 128 + k] = __uint_as_float(lb);
  }
}

// ---------------------------------------------------------------------------
// Kernel 1: conv 3x3 s1 p1 (unchanged: ~92% of fp32 FFMA roofline)
// ---------------------------------------------------------------------------
__global__ __launch_bounds__(256) void conv1_kernel(
    const float* __restrict__ x, const float* __restrict__ nu,
    const float* __restrict__ b1) {
  __shared__ float sIn[180];
  __shared__ float4 sW[288];
  const int t = threadIdx.x;
  const int bx = blockIdx.x, by = blockIdx.y, b = blockIdx.z;
  const float nf = nu[0] * 0.5f;

  const int og = t >> 4;
  const int p  = t & 15;
  const int row = p >> 1;
  const int cbase = (p & 1) * 8;
  const int r0 = by * 8, c0 = bx * 16;

  const int lr = t / 18, lc = t % 18;
  const int gy = r0 - 1 + lr, gx = c0 - 1 + lc;
  const bool inb = (t < 180) && (gy >= 0) && (gy < HH) && (gx >= 0) && (gx < HH);
  const long xoff = ((long)b * 256) * PIX + (long)gy * HH + gx;

  float acc[64];
#pragma unroll
  for (int i = 0; i < 64; ++i) acc[i] = 0.f;

  const float4* wp4 = (const float4*)g_wp;

  {
    float v = 0.f;
    if (inb) v = x[xoff];
    float4 wa = wp4[t];
    float4 wb;
    if (t < 32) wb = wp4[256 + t];
    if (t < 180) sIn[t] = v;
    sW[t] = wa;
    if (t < 32) sW[256 + t] = wb;
  }
  __syncthreads();

  float pin = 0.f;
  float4 pwa, pwb;

  for (int ic = 0; ic < 257; ++ic) {
    if (ic < 256) {
      const int icn = ic + 1;
      pin = 0.f;
      if (inb) pin = (icn < 256) ? x[xoff + (long)icn * PIX] : nf;
      pwa = wp4[icn * 288 + t];
      if (t < 32) pwb = wp4[icn * 288 + 256 + t];
    }
#pragma unroll
    for (int kh = 0; kh < 3; ++kh) {
      float inr[10];
#pragma unroll
      for (int j = 0; j < 10; ++j) inr[j] = sIn[(row + kh) * 18 + cbase + j];
#pragma unroll
      for (int kw = 0; kw < 3; ++kw) {
        const int kk = kh * 3 + kw;
        const float4 wa = sW[kk * 32 + og * 2];
        const float4 wb = sW[kk * 32 + og * 2 + 1];
#pragma unroll
        for (int j = 0; j < 8; ++j) {
          const float iv = inr[kw + j];
          acc[0 * 8 + j] += wa.x * iv;
          acc[1 * 8 + j] += wa.y * iv;
          acc[2 * 8 + j] += wa.z * iv;
          acc[3 * 8 + j] += wa.w * iv;
          acc[4 * 8 + j] += wb.x * iv;
          acc[5 * 8 + j] += wb.y * iv;
          acc[6 * 8 + j] += wb.z * iv;
          acc[7 * 8 + j] += wb.w * iv;
        }
      }
    }
    __syncthreads();
    if (ic < 256) {
      if (t < 180) sIn[t] = pin;
      sW[t] = pwa;
      if (t < 32) sW[256 + t] = pwb;
    }
    __syncthreads();
  }

  if (c0 + cbase < HH) {
#pragma unroll
    for (int ocl = 0; ocl < 8; ++ocl) {
      const int oc = og * 8 + ocl;
      const float bb = b1[oc];
      float* dst = g_z + ((b * 128 + oc) * HH + r0 + row) * HH + c0 + cbase;
      float4 v0 = {acc[ocl*8+0]+bb, acc[ocl*8+1]+bb, acc[ocl*8+2]+bb, acc[ocl*8+3]+bb};
      float4 v1 = {acc[ocl*8+4]+bb, acc[ocl*8+5]+bb, acc[ocl*8+6]+bb, acc[ocl*8+7]+bb};
      ((float4*)dst)[0] = v0;
      ((float4*)dst)[1] = v1;
    }
  }
}

// ---------------------------------------------------------------------------
// Kernel 2: BN1 stats
// ---------------------------------------------------------------------------
__global__ __launch_bounds__(256) void stats1_kernel() {
  const int c = blockIdx.x, t = threadIdx.x;
  double s = 0.0, q = 0.0;
  for (int i = t; i < N1; i += 256) {
    int b = i / PIX, p = i % PIX;
    float v = g_z[(b * 128 + c) * PIX + p];
    s += v; q += (double)v * v;
  }
  __shared__ double ss[256], sq[256];
  ss[t] = s; sq[t] = q;
  __syncthreads();
  for (int o = 128; o > 0; o >>= 1) {
    if (t < o) { ss[t] += ss[t + o]; sq[t] += sq[t + o]; }
    __syncthreads();
  }
  if (t == 0) {
    double m   = ss[0] / N1;
    double var = sq[0] / N1 - m * m;
    g_m1[c]  = (float)m;
    g_rs1[c] = rsqrtf((float)var + 1e-5f);
  }
}

// ---------------------------------------------------------------------------
// Threefry2x32, key (0,42), partitionable draw: x0=0, x1=j, out = o0^o1.
// ---------------------------------------------------------------------------
__device__ __forceinline__ unsigned tf_xor(unsigned j) {
  const unsigned ks0 = 0u, ks1 = 42u, ks2 = 0x1BD11BDAu ^ 42u;
  unsigned x0 = 0u + ks0;
  unsigned x1 = j  + ks1;
#define TFRND(r) { x0 += x1; x1 = __funnelshift_l(x1, x1, r); x1 ^= x0; }
  TFRND(13) TFRND(15) TFRND(26) TFRND(6)
  x0 += ks1; x1 += ks2 + 1u;
  TFRND(17) TFRND(29) TFRND(16) TFRND(24)
  x0 += ks2; x1 += ks0 + 2u;
  TFRND(13) TFRND(15) TFRND(26) TFRND(6)
  x0 += ks0; x1 += ks1 + 3u;
  TFRND(17) TFRND(29) TFRND(16) TFRND(24)
  x0 += ks1; x1 += ks2 + 4u;
  TFRND(13) TFRND(15) TFRND(26) TFRND(6)
  x0 += ks2; x1 += ks0 + 5u;
#undef TFRND
  return x0 ^ x1;
}

// ---------------------------------------------------------------------------
// Kernel 3: BN1 apply + sigmoid + quantize + BEC (in place on g_z)
// ---------------------------------------------------------------------------
__global__ __launch_bounds__(256) void bec_kernel(
    const float* __restrict__ nu, const float* __restrict__ g1,
    const float* __restrict__ be1) {
  const int e = blockIdx.x * 256 + threadIdx.x;
  const int c = (e / PIX) & 127;
  const float z = g_z[e];
  float tt = (z - g_m1[c]) * g_rs1[c] * g1[c] + be1[c];
  float s  = 0.5f * tanhf(0.5f * tt) + 0.5f;
  float r  = rintf(s * 256.0f);
  if (r >= 256.0f) r -= 256.0f;
  const unsigned xb = (unsigned)r;

  const float q = 1.0f - nu[0] * 0.5f;
  unsigned mask = 0u;
#pragma unroll
  for (int k = 0; k < 8; ++k) {
    unsigned bits = tf_xor((unsigned)(k * EZ + e));
    float u = __uint_as_float((bits >> 9) | 0x3f800000u) - 1.0f;
    if (u < q) mask |= (1u << k);
  }
  float outv = ((float)(xb & mask) + (255.0f - (float)mask) / 2.0f) / 255.0f;
  g_z[e] = outv;
}

// ---------------------------------------------------------------------------
// Kernel 4: decoder GEMM on warp-level mma.sync (tf32, A split hi/lo).
// Per block: 128m x 128n tile, K=128 fully staged.  8 warps = 2m x 4n,
// warp tile 64m x 32n -> 16 mma(m16n8k8) per K-step, 16 K-steps x {hi,lo}.
// grid = (25 n-tiles, 8 m-tiles, 32 batch).
// ---------------------------------------------------------------------------
#define SA_STR 132
#define SB_STR 133
#define SM_AH_F 0
#define SM_AL_F (128*SA_STR)
#define SM_B_F  (2*128*SA_STR)
#define SM_TOTF (2*128*SA_STR + 128*SB_STR)
#define SM_TOTB (SM_TOTF*4)

__global__ __launch_bounds__(256) void dec_mma_kernel(
    const float* __restrict__ b4, float* __restrict__ out) {
  extern __shared__ float sm[];
  float* sAh = sm + SM_AH_F;
  float* sAl = sm + SM_AL_F;
  float* sB  = sm + SM_B_F;

  const int t = threadIdx.x;
  const int lane = t & 31, wid = t >> 5;
  const int wm = wid >> 2, wn = wid & 3;     // 2 x 4 warp grid
  const int g = lane >> 2, tig = lane & 3;   // mma fragment coords
  const int nb   = blockIdx.x * 128;          // pixel base
  const int mblk = blockIdx.y;                // m-tile (128 rows of 1024)
  const int b    = blockIdx.z;

  // stage A hi/lo [m][k]
  for (int i = t; i < 128 * 128; i += 256) {
    int m = i >> 7, k = i & 127;
    int gi = (mblk * 128 + m) * 128 + k;
    sAh[m * SA_STR + k] = g_Ah[gi];
    sAl[m * SA_STR + k] = g_Al[gi];
  }
  // stage B transposed: sB[n][k] = h[k][nb+n], zero-pad past PIX
  for (int i = t; i < 128 * 128; i += 256) {
    int k = i >> 7, n = i & 127;
    float v = 0.f;
    if (nb + n < PIX) v = g_z[(b * 128 + k) * PIX + nb + n];
    sB[n * SB_STR + k] = v;
  }
  __syncthreads();

  float acc[4][4][4];
#pragma unroll
  for (int mt = 0; mt < 4; ++mt)
#pragma unroll
    for (int nt = 0; nt < 4; ++nt)
#pragma unroll
      for (int j = 0; j < 4; ++j) acc[mt][nt][j] = 0.f;

#define MMA(d, a, b0, b1)                                                     \
  asm volatile(                                                               \
      "mma.sync.aligned.m16n8k8.row.col.f32.tf32.tf32.f32 "                   \
      "{%0,%1,%2,%3}, {%4,%5,%6,%7}, {%8,%9}, {%0,%1,%2,%3};"                 \
      : "+f"((d)[0]), "+f"((d)[1]), "+f"((d)[2]), "+f"((d)[3])                \
      : "r"((a)[0]), "r"((a)[1]), "r"((a)[2]), "r"((a)[3]), "r"(b0), "r"(b1))

  for (int ks = 0; ks < 16; ++ks) {
    const int kb = ks * 8;
    // B fragments (shared by hi and lo passes)
    uint32_t bf[4][2];
#pragma unroll
    for (int nt = 0; nt < 4; ++nt) {
      const float* p = sB + (wn * 32 + nt * 8 + g) * SB_STR + kb + tig;
      bf[nt][0] = __float_as_uint(p[0]);
      bf[nt][1] = __float_as_uint(p[4]);
    }
    // A hi fragments + mma
    uint32_t af[4][4];
#pragma unroll
    for (int mt = 0; mt < 4; ++mt) {
      const float* p = sAh + (wm * 64 + mt * 16 + g) * SA_STR + kb + tig;
      af[mt][0] = __float_as_uint(p[0]);
      af[mt][1] = __float_as_uint(p[8 * SA_STR]);
      af[mt][2] = __float_as_uint(p[4]);
      af[mt][3] = __float_as_uint(p[8 * SA_STR + 4]);
    }
#pragma unroll
    for (int mt = 0; mt < 4; ++mt)
#pragma unroll
      for (int nt = 0; nt < 4; ++nt) MMA(acc[mt][nt], af[mt], bf[nt][0], bf[nt][1]);
    // A lo fragments + mma
#pragma unroll
    for (int mt = 0; mt < 4; ++mt) {
      const float* p = sAl + (wm * 64 + mt * 16 + g) * SA_STR + kb + tig;
      af[mt][0] = __float_as_uint(p[0]);
      af[mt][1] = __float_as_uint(p[8 * SA_STR]);
      af[mt][2] = __float_as_uint(p[4]);
      af[mt][3] = __float_as_uint(p[8 * SA_STR + 4]);
    }
#pragma unroll
    for (int mt = 0; mt < 4; ++mt)
#pragma unroll
      for (int nt = 0; nt < 4; ++nt) MMA(acc[mt][nt], af[mt], bf[nt][0], bf[nt][1]);
  }
#undef MMA

  // epilogue: m = c*4 + th*2 + tw ; pix -> 2x2 scatter, + bias
#pragma unroll
  for (int mt = 0; mt < 4; ++mt) {
#pragma unroll
    for (int half = 0; half < 2; ++half) {
      const int m = mblk * 128 + wm * 64 + mt * 16 + g + half * 8;
      const int c = m >> 2, th = (m >> 1) & 1, tw = m & 1;
      const float bb = b4[c];
      float* orow = out + ((b * 256 + c) * OHH + th) * OHH + tw;
#pragma unroll
      for (int nt = 0; nt < 4; ++nt) {
        const int n0 = nb + wn * 32 + nt * 8 + tig * 2;
#pragma unroll
        for (int jj = 0; jj < 2; ++jj) {
          const int pix = n0 + jj;
          if (pix < PIX) {
            const int ih = pix / HH, iw = pix - ih * HH;
            orow[(2 * ih) * OHH + 2 * iw] = acc[mt][nt][half * 2 + jj] + bb;
          }
        }
      }
    }
  }
}

// ---------------------------------------------------------------------------
// Kernel 5: BN2 stats
// ---------------------------------------------------------------------------
__global__ __launch_bounds__(256) void stats2_kernel(const float* __restrict__ out) {
  const int c = blockIdx.x, t = threadIdx.x;
  double s = 0.0, q = 0.0;
  for (int i = t; i < N2 / 4; i += 256) {
    int b = i / (OPIX / 4), p4 = i % (OPIX / 4);
    float4 v = *(const float4*)(out + (b * 256 + c) * OPIX + p4 * 4);
    s += (double)v.x + v.y + v.z + v.w;
    q += (double)v.x * v.x + (double)v.y * v.y +
         (double)v.z * v.z + (double)v.w * v.w;
  }
  __shared__ double ss[256], sq[256];
  ss[t] = s; sq[t] = q;
  __syncthreads();
  for (int o = 128; o > 0; o >>= 1) {
    if (t < o) { ss[t] += ss[t + o]; sq[t] += sq[t + o]; }
    __syncthreads();
  }
  if (t == 0) {
    double m   = ss[0] / N2;
    double var = sq[0] / N2 - m * m;
    g_m2[c]  = (float)m;
    g_rs2[c] = rsqrtf((float)var + 1e-5f);
  }
}

// ---------------------------------------------------------------------------
// Kernel 6: BN2 apply + relu, in place on d_out
// ---------------------------------------------------------------------------
__global__ __launch_bounds__(256) void bn2_kernel(
    const float* __restrict__ g2, const float* __restrict__ be2,
    float* __restrict__ out) {
  const int i = blockIdx.x * 256 + threadIdx.x;
  const int c = (i / (OPIX / 4)) & 255;
  float4 v = ((float4*)out)[i];
  const float m = g_m2[c], rs = g_rs2[c], gg = g2[c], bb = be2[c];
  v.x = fmaxf((v.x - m) * rs * gg + bb, 0.f);
  v.y = fmaxf((v.y - m) * rs * gg + bb, 0.f);
  v.z = fmaxf((v.z - m) * rs * gg + bb, 0.f);
  v.w = fmaxf((v.w - m) * rs * gg + bb, 0.f);
  ((float4*)out)[i] = v;
}

// ---------------------------------------------------------------------------
extern "C" void kernel_launch(void* const* d_in, const int* in_sizes, int n_in,
                              void* d_out, int out_size) {
  const float* x   = (const float*)d_in[0];
  const float* nu  = (const float*)d_in[1];
  const float* w1  = (const float*)d_in[2];
  const float* b1  = (const float*)d_in[3];
  const float* g1  = (const float*)d_in[4];
  const float* be1 = (const float*)d_in[5];
  const float* w4  = (const float*)d_in[6];
  const float* b4  = (const float*)d_in[7];
  const float* g2  = (const float*)d_in[8];
  const float* be2 = (const float*)d_in[9];
  float* out = (float*)d_out;

  cudaFuncSetAttribute(dec_mma_kernel, cudaFuncAttributeMaxDynamicSharedMemorySize, SM_TOTB);

  repack_kernel<<<(KW1 * 128 + 255) / 256, 256>>>(w1);
  prepA_kernel<<<(1024 * 128) / 256, 256>>>(w4);
  conv1_kernel<<<dim3(4, 7, 32), 256>>>(x, nu, b1);
  stats1_kernel<<<128, 256>>>();
  bec_kernel<<<EZ / 256, 256>>>(nu, g1, be1);
  dec_mma_kernel<<<dim3(25, 8, 32), 256, SM_TOTB>>>(b4, out);
  stats2_kernel<<<256, 256>>>(out);
  bn2_kernel<<<out_size / 4 / 256, 256>>>(g2, be2, out);
}